// round 14
// baseline (speedup 1.0000x reference)
#include <cuda_runtime.h>
#include <cstdint>

#define NQ   22
#define DIM  (1u << NQ)     // 4194304 elements per component

// ---- tiny diagonal split tables (device globals, no allocation) ----
// diag[b] = dLo[b&2047] + dHi[b>>11] + sum_{h set in (b>>11)} R[h][b&2047]
// Written by K2's CTAs (x<4, y==0); read by K1 (next launch).
__device__ float g_dLo[2048];
__device__ float g_dHi[2048];
__device__ float g_R[11][2048];

__device__ __forceinline__ void add4(float4& a, const float4 b) {
    a.x += b.x; a.y += b.y; a.z += b.z; a.w += b.w;
}

__device__ __forceinline__ uint32_t smem_u32(const void* p) {
    uint32_t a;
    asm("{ .reg .u64 t; cvta.to.shared.u64 t, %1; cvt.u32.u64 %0, t; }"
        : "=r"(a) : "l"(p));
    return a;
}
__device__ __forceinline__ void cpasync16(uint32_t s, const void* g) {
    asm volatile("cp.async.cg.shared.global [%0], [%1], 16;" :: "r"(s), "l"(g));
}
#define CP_COMMIT() asm volatile("cp.async.commit_group;")
#define CP_WAIT0()  asm volatile("cp.async.wait_group 0;")

// ---------------------------------------------------------------------------
// Inline table computation (inside K2's CTAs x<4, y==0; 512 entries per CTA).
// Branch-free FMAs on __ldg(U) (warp-uniform broadcast, L1-hot).
// ---------------------------------------------------------------------------
__device__ __forceinline__ float bitf(int t, int q) {
    return (float)((t >> q) & 1);
}

__device__ void compute_tables_inline(const float* __restrict__ U,
                                      const float* __restrict__ detune)
{
    const int t = ((int)blockIdx.x << 9) + threadIdx.x;   // 0..2047
    const float det = __ldg(detune);

    float dlo0 = 0.f, dlo1 = 0.f;
#pragma unroll
    for (int p = 0; p < 11; p++) {
        float rs = -det;
#pragma unroll
        for (int q = 0; q < p; q++)
            rs = fmaf(bitf(t, q), __ldg(&U[(21 - p) * NQ + (21 - q)]), rs);
        if (p & 1) dlo1 = fmaf(bitf(t, p), rs, dlo1);
        else       dlo0 = fmaf(bitf(t, p), rs, dlo0);
    }
    g_dLo[t] = dlo0 + dlo1;

    float dhi0 = 0.f, dhi1 = 0.f;
#pragma unroll
    for (int h = 0; h < 11; h++) {
        float rs = -det;
#pragma unroll
        for (int h2 = 0; h2 < h; h2++)
            rs = fmaf(bitf(t, h2), __ldg(&U[(10 - h) * NQ + (10 - h2)]), rs);
        if (h & 1) dhi1 = fmaf(bitf(t, h), rs, dhi1);
        else       dhi0 = fmaf(bitf(t, h), rs, dhi0);
    }
    g_dHi[t] = dhi0 + dhi1;

#pragma unroll
    for (int h = 0; h < 11; h++) {
        float r0 = 0.f, r1 = 0.f;
#pragma unroll
        for (int q = 0; q < 11; q += 2)
            r0 = fmaf(bitf(t, q), __ldg(&U[(10 - h) * NQ + (21 - q)]), r0);
#pragma unroll
        for (int q = 1; q < 11; q += 2)
            r1 = fmaf(bitf(t, q), __ldg(&U[(10 - h) * NQ + (21 - q)]), r1);
        g_R[h][t] = r0 + r1;
    }
}

// ---------------------------------------------------------------------------
// K2 (RUNS FIRST): high bits 14..21 (8 X-neighbors); WRITES out = c*acc_high.
//   Component-split (blockIdx.y). blockIdx.x = b21<<9 | mid, mid = elem bits
//   5..13, b21 = elem bit 21. Tile = 128 combos (bits 14..20) x 32-elem rows
//   (128B) = 16KB. 512 threads, 2 f4/thread.
//   bits 14..19: 6 smem dirs; bit 20: reg dir; bit 21: global dir prefetched.
//   CTAs (x<4, y==0) additionally compute the diag tables for K1.
// ---------------------------------------------------------------------------
__global__ void __launch_bounds__(512, 3)
k2_high_kernel(const float* __restrict__ sr, const float* __restrict__ si,
               const float* __restrict__ rabi, float* __restrict__ out,
               const float* __restrict__ U, const float* __restrict__ detune)
{
    extern __shared__ float4 sv[];     // 1024 f4 = 16KB (one component)
    const uint32_t sb = smem_u32(sv);
    const int tid = threadIdx.x;
    const int comp = blockIdx.y;
    const unsigned mid = blockIdx.x & 511u;          // elem bits 5..13
    const unsigned b21 = blockIdx.x >> 9;            // elem bit 21
    const float4* g4 = (const float4*)(comp ? si : sr);
    float4* o4 = (float4*)(out + (unsigned)comp * DIM);

    const unsigned gG0 = (b21 << 19) + ((unsigned)(tid >> 3) << 12) + (mid << 3) + (tid & 7);
    const unsigned gG1 = gG0 + (64u << 12);          // idx + 512 -> c7 += 64

    cpasync16(sb + tid * 16, g4 + gG0);
    cpasync16(sb + (tid + 512) * 16, g4 + gG1);
    CP_COMMIT();
    const float c = 0.5f * __ldg(rabi);

    // bit-21 global neighbors prefetched behind the fill
    float4 n0 = __ldg(&g4[gG0 ^ (1u << 19)]);
    float4 n1 = __ldg(&g4[gG1 ^ (1u << 19)]);

    // side job: 4 CTAs build the diag tables for K1 (next kernel)
    if (blockIdx.x < 4 && comp == 0) compute_tables_inline(U, detune);

    CP_WAIT0();
    __syncthreads();

    float4 v0 = sv[tid];
    float4 v1 = sv[tid + 512];

    // ---- k = 0 ----
    {
        const int idx = tid;
        float4 t0 = sv[idx ^ 8],   t1 = sv[idx ^ 16],  t2 = sv[idx ^ 32];
        float4 t3 = sv[idx ^ 64],  t4 = sv[idx ^ 128], t5 = sv[idx ^ 256];
        add4(t0, t1); add4(t2, t3); add4(t4, t5);
        add4(t0, v1);                   // reg dir (bit 20)
        add4(t2, n0);                   // global dir (bit 21)
        add4(t0, t2); add4(t0, t4);
        o4[gG0] = make_float4(c * t0.x, c * t0.y, c * t0.z, c * t0.w);
    }
    // ---- k = 1 ----
    {
        const int idx = tid + 512;
        float4 t0 = sv[idx ^ 8],   t1 = sv[idx ^ 16],  t2 = sv[idx ^ 32];
        float4 t3 = sv[idx ^ 64],  t4 = sv[idx ^ 128], t5 = sv[idx ^ 256];
        add4(t0, t1); add4(t2, t3); add4(t4, t5);
        add4(t0, v0);                   // reg dir (bit 20)
        add4(t2, n1);                   // global dir (bit 21)
        add4(t0, t2); add4(t0, t4);
        o4[gG1] = make_float4(c * t0.x, c * t0.y, c * t0.z, c * t0.w);
    }
}

// ---------------------------------------------------------------------------
// K1 (RUNS SECOND): low bits 0..13 (14 X-neighbors) + FULL diagonal; RMW:
//   out += c*acc_low + diag .* psi.
//   Component-split (blockIdx.y). Tile = 8192 consecutive elems = 32KB =
//   2048 f4 -> 3 CTAs/SM. 512 threads, 4 f4/thread: G = tid + k*512
//   (k = elem bits 11..12). bx = elem bits 13..21 (grid.x = 512).
//   bits 0..1  : in-float4 swaps
//   bits 2..12 : 11 smem XOR dirs (incl. G^512, G^1024 — former reg dirs)
//   bit 13     : coalesced GLOBAL dir (gG ^ 2048, L2-resident)
//   diag: lo4 = tid*4 fixed; D0 = dLo + bx-masked R rows 2..10 (staged
//   behind the fill); R0/R1 per-k L1 reloads; dHi scalar per k.
//   No v[] register cache (fits the 42-reg cap of (512,3)).
// ---------------------------------------------------------------------------
__global__ void __launch_bounds__(512, 3)
k1_low_kernel(const float* __restrict__ sr, const float* __restrict__ si,
              const float* __restrict__ rabi, float* __restrict__ out)
{
    extern __shared__ float4 sv[];     // 2048 f4 = 32KB (one component)
    const uint32_t sb = smem_u32(sv);
    const int tid = threadIdx.x;
    const int bx = blockIdx.x;                       // elem bits 13..21
    const int comp = blockIdx.y;
    const float4* g4 = (const float4*)(comp ? si : sr);
    float4* o4 = (float4*)(out + (unsigned)comp * DIM);
    const unsigned gbase = (unsigned)bx << 11;       // f4-group base

#pragma unroll
    for (int j = 0; j < 4; j++) {
        const int idx = tid + j * 512;
        cpasync16(sb + idx * 16, g4 + gbase + idx);
    }
    CP_COMMIT();
    const float c = 0.5f * __ldg(rabi);

    // ---- diag staging: L1/L2 loads overlap the cp.async fill ----
    const int lo4 = tid << 2;                        // elem bits 0..10, f4 base
    float4 D0 = __ldg((const float4*)&g_dLo[lo4]);
#pragma unroll
    for (int t = 0; t < 9; t++)
        if ((bx >> t) & 1) add4(D0, __ldg((const float4*)&g_R[t + 2][lo4]));

    CP_WAIT0();
    __syncthreads();

#pragma unroll
    for (int k = 0; k < 4; k++) {
        const int G = tid + k * 512;
        const unsigned gG = gbase + G;

        // RMW target + bit-13 global neighbor issued first (L2 latency
        // overlaps the smem dir block below)
        float4 o = o4[gG];
        float4 n = __ldg(&g4[gG ^ 2048u]);

        const float4 s = sv[G];
        // elem bits 0..1 (in-float4)
        float4 a = make_float4(s.y + s.z, s.x + s.w, s.w + s.x, s.z + s.y);

        // 11 smem dirs: bits 2..10 (G^1..G^256) + bits 11..12 (G^512,G^1024)
        float4 d0 = sv[G ^ 1],  d1 = sv[G ^ 2],  d2 = sv[G ^ 4],  d3 = sv[G ^ 8];
        add4(d0, d1); add4(d2, d3);
        add4(a, d0);  add4(a, d2);
        float4 e0 = sv[G ^ 16], e1 = sv[G ^ 32], e2 = sv[G ^ 64], e3 = sv[G ^ 128];
        add4(e0, e1); add4(e2, e3);
        add4(a, e0);  add4(a, e2);
        float4 f0 = sv[G ^ 256], f1 = sv[G ^ 512], f2 = sv[G ^ 1024];
        add4(f0, f1); add4(a, f2);
        add4(a, f0);  add4(a, n);       // + bit-13 global dir

        // diagonal weight (k compile-time -> predicated L1 reloads)
        float4 W = D0;
        if (k & 1) add4(W, __ldg((const float4*)&g_R[0][lo4]));
        if (k & 2) add4(W, __ldg((const float4*)&g_R[1][lo4]));
        const float dh = __ldg(&g_dHi[((unsigned)bx << 2) | k]);
        W.x += dh; W.y += dh; W.z += dh; W.w += dh;

        o.x = fmaf(c, a.x, fmaf(W.x, s.x, o.x));
        o.y = fmaf(c, a.y, fmaf(W.y, s.y, o.y));
        o.z = fmaf(c, a.z, fmaf(W.z, s.z, o.z));
        o.w = fmaf(c, a.w, fmaf(W.w, s.w, o.w));
        o4[gG] = o;
    }
}

// ---------------------------------------------------------------------------
// Launch: K2 (bits 14..21, writes out; 4 CTAs build tables)
//      -> K1 (bits 0..13 + diag, RMW out, 32KB tiles / 3 CTAs per SM).
// ---------------------------------------------------------------------------
extern "C" void kernel_launch(void* const* d_in, const int* in_sizes, int n_in,
                              void* d_out, int out_size)
{
    const float* sr     = (const float*)d_in[0];
    const float* si     = (const float*)d_in[1];
    const float* rabi   = (const float*)d_in[2];
    const float* detune = (const float*)d_in[3];
    const float* U      = (const float*)d_in[4];
    float* out = (float*)d_out;

    cudaFuncSetAttribute(k1_low_kernel,
                         cudaFuncAttributeMaxDynamicSharedMemorySize, 32768);
    cudaFuncSetAttribute(k2_high_kernel,
                         cudaFuncAttributeMaxDynamicSharedMemorySize, 16384);

    k2_high_kernel<<<dim3(1024, 2), 512, 16384>>>(sr, si, rabi, out, U, detune);
    k1_low_kernel<<<dim3(512, 2), 512, 32768>>>(sr, si, rabi, out);
}

// round 15
// speedup vs baseline: 1.2065x; 1.2065x over previous
#include <cuda_runtime.h>
#include <cstdint>

#define NQ   22
#define DIM  (1u << NQ)     // 4194304 elements per component

// ---- tiny diagonal split tables (device globals, no allocation) ----
// diag[b] = dLo[b&2047] + dHi[b>>11] + sum_{h set in (b>>11)} R[h][b&2047]
// Written by K1's CTAs (x<4, y==0); read by K2 (next launch).
__device__ float g_dLo[2048];
__device__ float g_dHi[2048];
__device__ float g_R[11][2048];

__device__ __forceinline__ void add4(float4& a, const float4 b) {
    a.x += b.x; a.y += b.y; a.z += b.z; a.w += b.w;
}

__device__ __forceinline__ uint32_t smem_u32(const void* p) {
    uint32_t a;
    asm("{ .reg .u64 t; cvta.to.shared.u64 t, %1; cvt.u32.u64 %0, t; }"
        : "=r"(a) : "l"(p));
    return a;
}
__device__ __forceinline__ void cpasync16(uint32_t s, const void* g) {
    asm volatile("cp.async.cg.shared.global [%0], [%1], 16;" :: "r"(s), "l"(g));
}
#define CP_COMMIT() asm volatile("cp.async.commit_group;")
#define CP_WAIT0()  asm volatile("cp.async.wait_group 0;")

// ---------------------------------------------------------------------------
// Inline table computation (inside K1's CTAs x<4, y==0; 512 entries per CTA).
// Branch-free FMAs on __ldg(U) (warp-uniform broadcast, L1-hot). Runs while
// the CTA's cp.async fill is in flight -> effectively free.
// ---------------------------------------------------------------------------
__device__ __forceinline__ float bitf(int t, int q) {
    return (float)((t >> q) & 1);
}

__device__ void compute_tables_inline(const float* __restrict__ U,
                                      const float* __restrict__ detune)
{
    const int t = ((int)blockIdx.x << 9) + threadIdx.x;   // 0..2047
    const float det = __ldg(detune);

    float dlo0 = 0.f, dlo1 = 0.f;
#pragma unroll
    for (int p = 0; p < 11; p++) {
        float rs = -det;
#pragma unroll
        for (int q = 0; q < p; q++)
            rs = fmaf(bitf(t, q), __ldg(&U[(21 - p) * NQ + (21 - q)]), rs);
        if (p & 1) dlo1 = fmaf(bitf(t, p), rs, dlo1);
        else       dlo0 = fmaf(bitf(t, p), rs, dlo0);
    }
    g_dLo[t] = dlo0 + dlo1;

    float dhi0 = 0.f, dhi1 = 0.f;
#pragma unroll
    for (int h = 0; h < 11; h++) {
        float rs = -det;
#pragma unroll
        for (int h2 = 0; h2 < h; h2++)
            rs = fmaf(bitf(t, h2), __ldg(&U[(10 - h) * NQ + (10 - h2)]), rs);
        if (h & 1) dhi1 = fmaf(bitf(t, h), rs, dhi1);
        else       dhi0 = fmaf(bitf(t, h), rs, dhi0);
    }
    g_dHi[t] = dhi0 + dhi1;

#pragma unroll
    for (int h = 0; h < 11; h++) {
        float r0 = 0.f, r1 = 0.f;
#pragma unroll
        for (int q = 0; q < 11; q += 2)
            r0 = fmaf(bitf(t, q), __ldg(&U[(10 - h) * NQ + (21 - q)]), r0);
#pragma unroll
        for (int q = 1; q < 11; q += 2)
            r1 = fmaf(bitf(t, q), __ldg(&U[(10 - h) * NQ + (21 - q)]), r1);
        g_R[h][t] = r0 + r1;
    }
}

// ---------------------------------------------------------------------------
// K1 (RUNS FIRST): low bits 0..13 (14 X-neighbors), NO diag, NO RMW;
//   writes out = c*acc_low. This is the measured-fastest form (~11us).
//   Component-split (blockIdx.y). Tile = 16384 consecutive elems = 64KB.
//   512 threads, 8 f4/thread reg-cached: G = tid + k*512 (k = bits 11..13).
//   bits 0..1: in-float4; bits 2..10: 9 smem dirs; bits 11..13: reg dirs.
//   CTAs (x<4, y==0) also build the diag tables for K2 behind their fill.
// ---------------------------------------------------------------------------
__global__ void __launch_bounds__(512, 2)
k1_low_kernel(const float* __restrict__ sr, const float* __restrict__ si,
              const float* __restrict__ rabi, float* __restrict__ out,
              const float* __restrict__ U, const float* __restrict__ detune)
{
    extern __shared__ float4 sv[];     // 4096 f4 = 64KB (one component)
    const uint32_t sb = smem_u32(sv);
    const int tid = threadIdx.x;
    const int comp = blockIdx.y;
    const float4* g4 = (const float4*)(comp ? si : sr);
    float4* o4 = (float4*)(out + (unsigned)comp * DIM);
    const unsigned gbase = (unsigned)blockIdx.x << 12;   // f4-group base

#pragma unroll
    for (int j = 0; j < 8; j++) {
        const int idx = tid + j * 512;
        cpasync16(sb + idx * 16, g4 + gbase + idx);
    }
    CP_COMMIT();
    const float c = 0.5f * __ldg(rabi);

    // side job: 4 CTAs build the diag tables for K2 while their fill flies
    if (blockIdx.x < 4 && comp == 0) compute_tables_inline(U, detune);

    CP_WAIT0();
    __syncthreads();

    float4 v[8];
#pragma unroll
    for (int k = 0; k < 8; k++) v[k] = sv[tid + k * 512];

#pragma unroll
    for (int k = 0; k < 8; k++) {
        const int G = tid + k * 512;
        const float4 s = v[k];

        // bits 0..1 (in-float4) + register dirs (bits 11..13)
        float4 a = make_float4(s.y + s.z, s.x + s.w, s.w + s.x, s.z + s.y);
        add4(a, v[k ^ 1]);
        add4(a, v[k ^ 2]);
        add4(a, v[k ^ 4]);

        // 9 smem dirs (bits 2..10), two waves to bound live temps
        float4 t0 = sv[G ^ 1],  t1 = sv[G ^ 2],  t2 = sv[G ^ 4];
        float4 t3 = sv[G ^ 8];
        add4(t0, t1); add4(t2, t3);
        add4(a, t0);  add4(a, t2);

        float4 u0 = sv[G ^ 16],  u1 = sv[G ^ 32],  u2 = sv[G ^ 64];
        float4 u3 = sv[G ^ 128], u4 = sv[G ^ 256];
        add4(u0, u1); add4(u2, u3);
        add4(u0, u2); add4(u4, a);
        add4(u4, u0);

        o4[gbase + G] = make_float4(c * u4.x, c * u4.y, c * u4.z, c * u4.w);
    }
}

// ---------------------------------------------------------------------------
// K2 (RUNS SECOND): high bits 14..21 (8 X-neighbors) + FULL diagonal; RMW:
//   out += c*acc_high + diag .* psi.
//   Component-split (blockIdx.y). blockIdx.x = b21<<9 | mid, mid = elem bits
//   5..13, b21 = elem bit 21. Tile = 128 combos (bits 14..20) x 32-elem rows
//   (128B) = 16KB. 512 threads, 2 f4/thread: idx = tid + k*512.
//   bits 14..19: 6 smem dirs; bit 20: reg dir (=k); bit 21: global dir.
//   DIAG IS NEARLY FREE HERE: per-thread lo f4 is fixed, and hi is fixed
//   except bit 9 (=k). base4 = dLo + all fixed-hi-bit R rows (predicated L1
//   loads behind the fill); W(k) = base4 + k*R[9] + dHi[hi_k].
// ---------------------------------------------------------------------------
__global__ void __launch_bounds__(512, 3)
k2_high_kernel(const float* __restrict__ sr, const float* __restrict__ si,
               const float* __restrict__ rabi, float* __restrict__ out)
{
    extern __shared__ float4 sv[];     // 1024 f4 = 16KB (one component)
    const uint32_t sb = smem_u32(sv);
    const int tid = threadIdx.x;
    const int comp = blockIdx.y;
    const unsigned mid = blockIdx.x & 511u;          // elem bits 5..13
    const unsigned b21 = blockIdx.x >> 9;            // elem bit 21
    const float4* g4 = (const float4*)(comp ? si : sr);
    float4* o4 = (float4*)(out + (unsigned)comp * DIM);

    const unsigned gG0 = (b21 << 19) + ((unsigned)(tid >> 3) << 12) + (mid << 3) + (tid & 7);
    const unsigned gG1 = gG0 + (64u << 12);          // idx + 512 -> combo += 64

    cpasync16(sb + tid * 16, g4 + gG0);
    cpasync16(sb + (tid + 512) * 16, g4 + gG1);
    CP_COMMIT();
    const float c = 0.5f * __ldg(rabi);

    // bit-21 global neighbors prefetched behind the fill
    float4 n0 = __ldg(&g4[gG0 ^ (1u << 19)]);
    float4 n1 = __ldg(&g4[gG1 ^ (1u << 19)]);

    // ---- diag staging (L1 loads, behind the fill) ----
    // lo (elem bits 0..10) fixed per thread: bits 2..4 = tid&7, 5..10 = mid&63
    const int lo4 = (int)((mid & 63u) << 5) | ((tid & 7) << 2);
    // hi (elem bits 11..21): bits 0..2 = mid>>6, 3..8 = (tid>>3)&63,
    // 9 = k (varies!), 10 = b21
    const unsigned midtop = mid >> 6;                // hi bits 0..2
    const unsigned c6 = ((unsigned)tid >> 3) & 63u;  // hi bits 3..8
    float4 base4 = __ldg((const float4*)&g_dLo[lo4]);
    if (midtop & 1) add4(base4, __ldg((const float4*)&g_R[0][lo4]));
    if (midtop & 2) add4(base4, __ldg((const float4*)&g_R[1][lo4]));
    if (midtop & 4) add4(base4, __ldg((const float4*)&g_R[2][lo4]));
#pragma unroll
    for (int t = 0; t < 6; t++)
        if ((c6 >> t) & 1) add4(base4, __ldg((const float4*)&g_R[t + 3][lo4]));
    if (b21) add4(base4, __ldg((const float4*)&g_R[10][lo4]));
    const float4 r9 = __ldg((const float4*)&g_R[9][lo4]);
    const unsigned hibase = midtop | (c6 << 3) | (b21 << 10);
    const float dh0 = __ldg(&g_dHi[hibase]);
    const float dh1 = __ldg(&g_dHi[hibase | (1u << 9)]);

    CP_WAIT0();
    __syncthreads();

    float4 v0 = sv[tid];
    float4 v1 = sv[tid + 512];

    // ---- k = 0 ----
    {
        const int idx = tid;
        float4 o = o4[gG0];             // RMW load overlaps the LDS block
        float4 t0 = sv[idx ^ 8],   t1 = sv[idx ^ 16],  t2 = sv[idx ^ 32];
        float4 t3 = sv[idx ^ 64],  t4 = sv[idx ^ 128], t5 = sv[idx ^ 256];
        add4(t0, t1); add4(t2, t3); add4(t4, t5);
        add4(t0, v1);                   // reg dir (bit 20)
        add4(t2, n0);                   // global dir (bit 21)
        add4(t0, t2); add4(t0, t4);

        float4 W = base4;
        W.x += dh0; W.y += dh0; W.z += dh0; W.w += dh0;
        o.x = fmaf(c, t0.x, fmaf(W.x, v0.x, o.x));
        o.y = fmaf(c, t0.y, fmaf(W.y, v0.y, o.y));
        o.z = fmaf(c, t0.z, fmaf(W.z, v0.z, o.z));
        o.w = fmaf(c, t0.w, fmaf(W.w, v0.w, o.w));
        o4[gG0] = o;
    }
    // ---- k = 1 ----
    {
        const int idx = tid + 512;
        float4 o = o4[gG1];
        float4 t0 = sv[idx ^ 8],   t1 = sv[idx ^ 16],  t2 = sv[idx ^ 32];
        float4 t3 = sv[idx ^ 64],  t4 = sv[idx ^ 128], t5 = sv[idx ^ 256];
        add4(t0, t1); add4(t2, t3); add4(t4, t5);
        add4(t0, v0);                   // reg dir (bit 20)
        add4(t2, n1);                   // global dir (bit 21)
        add4(t0, t2); add4(t0, t4);

        float4 W = base4;
        add4(W, r9);                    // hi bit 9 set for k=1
        W.x += dh1; W.y += dh1; W.z += dh1; W.w += dh1;
        o.x = fmaf(c, t0.x, fmaf(W.x, v1.x, o.x));
        o.y = fmaf(c, t0.y, fmaf(W.y, v1.y, o.y));
        o.z = fmaf(c, t0.z, fmaf(W.z, v1.z, o.z));
        o.w = fmaf(c, t0.w, fmaf(W.w, v1.w, o.w));
        o4[gG1] = o;
    }
}

// ---------------------------------------------------------------------------
// Launch: K1 (bits 0..13, writes out; 4 CTAs build tables)
//      -> K2 (bits 14..21 + diag, RMW out).
// ---------------------------------------------------------------------------
extern "C" void kernel_launch(void* const* d_in, const int* in_sizes, int n_in,
                              void* d_out, int out_size)
{
    const float* sr     = (const float*)d_in[0];
    const float* si     = (const float*)d_in[1];
    const float* rabi   = (const float*)d_in[2];
    const float* detune = (const float*)d_in[3];
    const float* U      = (const float*)d_in[4];
    float* out = (float*)d_out;

    cudaFuncSetAttribute(k1_low_kernel,
                         cudaFuncAttributeMaxDynamicSharedMemorySize, 65536);
    cudaFuncSetAttribute(k2_high_kernel,
                         cudaFuncAttributeMaxDynamicSharedMemorySize, 16384);

    k1_low_kernel<<<dim3(256, 2), 512, 65536>>>(sr, si, rabi, out, U, detune);
    k2_high_kernel<<<dim3(1024, 2), 512, 16384>>>(sr, si, rabi, out);
}

// round 16
// speedup vs baseline: 1.3538x; 1.1221x over previous
#include <cuda_runtime.h>
#include <cstdint>

#define NQ   22
#define DIM  (1u << NQ)     // 4194304 elements per component

// ---- tiny diagonal split tables (device globals, no allocation) ----
// diag[b] = dLo[b&2047] + dHi[b>>11] + sum_{h set in (b>>11)} R[h][b&2047]
// Written by K1's CTAs (x<4, y==0); read by K2 (next launch).
__device__ float g_dLo[2048];
__device__ float g_dHi[2048];
__device__ float g_R[11][2048];

__device__ __forceinline__ void add4(float4& a, const float4 b) {
    a.x += b.x; a.y += b.y; a.z += b.z; a.w += b.w;
}

__device__ __forceinline__ uint32_t smem_u32(const void* p) {
    uint32_t a;
    asm("{ .reg .u64 t; cvta.to.shared.u64 t, %1; cvt.u32.u64 %0, t; }"
        : "=r"(a) : "l"(p));
    return a;
}
__device__ __forceinline__ void cpasync16(uint32_t s, const void* g) {
    asm volatile("cp.async.cg.shared.global [%0], [%1], 16;" :: "r"(s), "l"(g));
}
#define CP_COMMIT() asm volatile("cp.async.commit_group;")
#define CP_WAIT0()  asm volatile("cp.async.wait_group 0;")

// ---------------------------------------------------------------------------
// Inline table computation (inside K1's CTAs x<4, y==0; 512 entries per CTA).
// Branch-free FMAs on __ldg(U) (warp-uniform broadcast, L1-hot); runs while
// the CTA's cp.async fill is in flight.
// ---------------------------------------------------------------------------
__device__ __forceinline__ float bitf(int t, int q) {
    return (float)((t >> q) & 1);
}

__device__ void compute_tables_inline(const float* __restrict__ U,
                                      const float* __restrict__ detune)
{
    const int t = ((int)blockIdx.x << 9) + threadIdx.x;   // 0..2047
    const float det = __ldg(detune);

    float dlo0 = 0.f, dlo1 = 0.f;
#pragma unroll
    for (int p = 0; p < 11; p++) {
        float rs = -det;
#pragma unroll
        for (int q = 0; q < p; q++)
            rs = fmaf(bitf(t, q), __ldg(&U[(21 - p) * NQ + (21 - q)]), rs);
        if (p & 1) dlo1 = fmaf(bitf(t, p), rs, dlo1);
        else       dlo0 = fmaf(bitf(t, p), rs, dlo0);
    }
    g_dLo[t] = dlo0 + dlo1;

    float dhi0 = 0.f, dhi1 = 0.f;
#pragma unroll
    for (int h = 0; h < 11; h++) {
        float rs = -det;
#pragma unroll
        for (int h2 = 0; h2 < h; h2++)
            rs = fmaf(bitf(t, h2), __ldg(&U[(10 - h) * NQ + (10 - h2)]), rs);
        if (h & 1) dhi1 = fmaf(bitf(t, h), rs, dhi1);
        else       dhi0 = fmaf(bitf(t, h), rs, dhi0);
    }
    g_dHi[t] = dhi0 + dhi1;

#pragma unroll
    for (int h = 0; h < 11; h++) {
        float r0 = 0.f, r1 = 0.f;
#pragma unroll
        for (int q = 0; q < 11; q += 2)
            r0 = fmaf(bitf(t, q), __ldg(&U[(10 - h) * NQ + (21 - q)]), r0);
#pragma unroll
        for (int q = 1; q < 11; q += 2)
            r1 = fmaf(bitf(t, q), __ldg(&U[(10 - h) * NQ + (21 - q)]), r1);
        g_R[h][t] = r0 + r1;
    }
}

// ---------------------------------------------------------------------------
// K1 (RUNS FIRST): low bits 0..13 (14 X-neighbors), NO diag, NO RMW;
//   writes out = c*acc_low. Measured-fastest form (~11.5us) — unchanged.
//   Component-split (blockIdx.y). Tile = 16384 consecutive elems = 64KB.
//   512 threads, 8 f4/thread reg-cached: G = tid + k*512 (k = bits 11..13).
//   bits 0..1: in-float4; bits 2..10: 9 smem dirs; bits 11..13: reg dirs.
//   CTAs (x<4, y==0) also build the diag tables for K2 behind their fill.
// ---------------------------------------------------------------------------
__global__ void __launch_bounds__(512, 2)
k1_low_kernel(const float* __restrict__ sr, const float* __restrict__ si,
              const float* __restrict__ rabi, float* __restrict__ out,
              const float* __restrict__ U, const float* __restrict__ detune)
{
    extern __shared__ float4 sv[];     // 4096 f4 = 64KB (one component)
    const uint32_t sb = smem_u32(sv);
    const int tid = threadIdx.x;
    const int comp = blockIdx.y;
    const float4* g4 = (const float4*)(comp ? si : sr);
    float4* o4 = (float4*)(out + (unsigned)comp * DIM);
    const unsigned gbase = (unsigned)blockIdx.x << 12;   // f4-group base

#pragma unroll
    for (int j = 0; j < 8; j++) {
        const int idx = tid + j * 512;
        cpasync16(sb + idx * 16, g4 + gbase + idx);
    }
    CP_COMMIT();
    const float c = 0.5f * __ldg(rabi);

    // side job: 4 CTAs build the diag tables for K2 while their fill flies
    if (blockIdx.x < 4 && comp == 0) compute_tables_inline(U, detune);

    CP_WAIT0();
    __syncthreads();

    float4 v[8];
#pragma unroll
    for (int k = 0; k < 8; k++) v[k] = sv[tid + k * 512];

#pragma unroll
    for (int k = 0; k < 8; k++) {
        const int G = tid + k * 512;
        const float4 s = v[k];

        // bits 0..1 (in-float4) + register dirs (bits 11..13)
        float4 a = make_float4(s.y + s.z, s.x + s.w, s.w + s.x, s.z + s.y);
        add4(a, v[k ^ 1]);
        add4(a, v[k ^ 2]);
        add4(a, v[k ^ 4]);

        // 9 smem dirs (bits 2..10), two waves to bound live temps
        float4 t0 = sv[G ^ 1],  t1 = sv[G ^ 2],  t2 = sv[G ^ 4];
        float4 t3 = sv[G ^ 8];
        add4(t0, t1); add4(t2, t3);
        add4(a, t0);  add4(a, t2);

        float4 u0 = sv[G ^ 16],  u1 = sv[G ^ 32],  u2 = sv[G ^ 64];
        float4 u3 = sv[G ^ 128], u4 = sv[G ^ 256];
        add4(u0, u1); add4(u2, u3);
        add4(u0, u2); add4(u4, a);
        add4(u4, u0);

        o4[gbase + G] = make_float4(c * u4.x, c * u4.y, c * u4.z, c * u4.w);
    }
}

// ---------------------------------------------------------------------------
// K2 (RUNS SECOND): high bits 14..21 (8 X-neighbors) + FULL diagonal; RMW:
//   out += c*acc_high + diag .* psi.
//   KEY CHANGE vs R15: the CTA loads BOTH bit-21 tiles (paired), so bit 21
//   becomes a register dir — the 32MB of global neighbor reads are gone and
//   each thread carries a 4-deep k pipeline.
//   Component-split (blockIdx.y). mid = blockIdx.x = elem bits 5..13 (512).
//   Smem tile = 128 combos (bits 14..20) x 32-elem rows x 2 (bit 21) = 32KB
//   = 2048 f4: idx = b21*1024 + combo*8 + rf8.
//   512 threads, 4 f4/thread: idx = tid + k*512 ->
//     rf8 = tid&7, combo bits 0..5 = (tid>>3)&63, combo bit 6 = k&1,
//     b21 = k>>1.
//   bits 14..19: 6 smem dirs (idx^8..idx^256); bit 20: v[k^1]; bit 21: v[k^2].
//   diag: lo fixed per thread; hi = midtop | c6<<3 | (k&1)<<9 | (k>>1)<<10.
//   base4 = dLo + midtop/c6-masked R rows (L1 loads behind the fill);
//   r9 applied when k&1; R[10] folded into base4 at k==2 (ascending loop).
// ---------------------------------------------------------------------------
__global__ void __launch_bounds__(512, 2)
k2_high_kernel(const float* __restrict__ sr, const float* __restrict__ si,
               const float* __restrict__ rabi, float* __restrict__ out)
{
    extern __shared__ float4 sv[];     // 2048 f4 = 32KB (one component, 2 tiles)
    const uint32_t sb = smem_u32(sv);
    const int tid = threadIdx.x;
    const int comp = blockIdx.y;
    const unsigned mid = blockIdx.x;                 // elem bits 5..13
    const float4* g4 = (const float4*)(comp ? si : sr);
    float4* o4 = (float4*)(out + (unsigned)comp * DIM);

    // global f4 index for thread's group k:
    //   gG(k) = c6<<12 | (k&1)<<18 | (k>>1)<<19 | mid<<3 | rf8
    const unsigned gbase = (((unsigned)tid >> 3) << 12) + (mid << 3) + (tid & 7u);

#pragma unroll
    for (int k = 0; k < 4; k++) {
        const unsigned gG = gbase | ((unsigned)(k & 1) << 18) | ((unsigned)(k >> 1) << 19);
        cpasync16(sb + (tid + k * 512) * 16, g4 + gG);
    }
    CP_COMMIT();
    const float c = 0.5f * __ldg(rabi);

    // ---- diag staging (L1 loads, behind the fill) ----
    const int lo4 = (int)((mid & 63u) << 5) | ((tid & 7) << 2);  // elem bits 0..10
    const unsigned midtop = mid >> 6;                // hi bits 0..2
    const unsigned c6 = ((unsigned)tid >> 3) & 63u;  // hi bits 3..8
    float4 base4 = __ldg((const float4*)&g_dLo[lo4]);
    if (midtop & 1) add4(base4, __ldg((const float4*)&g_R[0][lo4]));
    if (midtop & 2) add4(base4, __ldg((const float4*)&g_R[1][lo4]));
    if (midtop & 4) add4(base4, __ldg((const float4*)&g_R[2][lo4]));
#pragma unroll
    for (int t = 0; t < 6; t++)
        if ((c6 >> t) & 1) add4(base4, __ldg((const float4*)&g_R[t + 3][lo4]));
    const float4 r9 = __ldg((const float4*)&g_R[9][lo4]);
    const unsigned hibase = midtop | (c6 << 3);

    CP_WAIT0();
    __syncthreads();

    float4 v[4];
#pragma unroll
    for (int k = 0; k < 4; k++) v[k] = sv[tid + k * 512];

#pragma unroll
    for (int k = 0; k < 4; k++) {
        if (k == 2) add4(base4, __ldg((const float4*)&g_R[10][lo4]));  // fold R10
        const int idx = tid + k * 512;
        const unsigned gG = gbase | ((unsigned)(k & 1) << 18) | ((unsigned)(k >> 1) << 19);

        // RMW load issued first; L2 latency overlaps the LDS block
        float4 o = o4[gG];

        // 6 smem dirs (elem bits 14..19)
        float4 t0 = sv[idx ^ 8],   t1 = sv[idx ^ 16],  t2 = sv[idx ^ 32];
        float4 t3 = sv[idx ^ 64],  t4 = sv[idx ^ 128], t5 = sv[idx ^ 256];
        add4(t0, t1); add4(t2, t3); add4(t4, t5);
        add4(t0, v[k ^ 1]);             // reg dir (bit 20)
        add4(t2, v[k ^ 2]);             // reg dir (bit 21)
        add4(t0, t2); add4(t0, t4);

        // diagonal weight (k compile-time -> predicated adds are free)
        float4 W = base4;
        if (k & 1) add4(W, r9);
        const float dh = __ldg(&g_dHi[hibase | ((unsigned)(k & 1) << 9)
                                             | ((unsigned)(k >> 1) << 10)]);
        W.x += dh; W.y += dh; W.z += dh; W.w += dh;

        o.x = fmaf(c, t0.x, fmaf(W.x, v[k].x, o.x));
        o.y = fmaf(c, t0.y, fmaf(W.y, v[k].y, o.y));
        o.z = fmaf(c, t0.z, fmaf(W.z, v[k].z, o.z));
        o.w = fmaf(c, t0.w, fmaf(W.w, v[k].w, o.w));
        o4[gG] = o;
    }
}

// ---------------------------------------------------------------------------
// Launch: K1 (bits 0..13, writes out; 4 CTAs build tables)
//      -> K2 (bits 14..21 + diag, RMW out; bit-21 tiles paired in-CTA).
// ---------------------------------------------------------------------------
extern "C" void kernel_launch(void* const* d_in, const int* in_sizes, int n_in,
                              void* d_out, int out_size)
{
    const float* sr     = (const float*)d_in[0];
    const float* si     = (const float*)d_in[1];
    const float* rabi   = (const float*)d_in[2];
    const float* detune = (const float*)d_in[3];
    const float* U      = (const float*)d_in[4];
    float* out = (float*)d_out;

    cudaFuncSetAttribute(k1_low_kernel,
                         cudaFuncAttributeMaxDynamicSharedMemorySize, 65536);
    cudaFuncSetAttribute(k2_high_kernel,
                         cudaFuncAttributeMaxDynamicSharedMemorySize, 32768);

    k1_low_kernel<<<dim3(256, 2), 512, 65536>>>(sr, si, rabi, out, U, detune);
    k2_high_kernel<<<dim3(512, 2), 512, 32768>>>(sr, si, rabi, out);
}

// round 17
// speedup vs baseline: 1.4441x; 1.0667x over previous
#include <cuda_runtime.h>
#include <cstdint>

#define NQ   22
#define DIM  (1u << NQ)     // 4194304 elements per component

// ---- tiny diagonal split tables (device globals, no allocation) ----
// diag[b] = dLo[b&2047] + dHi[b>>11] + sum_{h set in (b>>11)} R[h][b&2047]
// Written by K1's CTAs (x<4, y==0); read by K2 (next launch).
__device__ float g_dLo[2048];
__device__ float g_dHi[2048];
__device__ float g_R[11][2048];

__device__ __forceinline__ void add4(float4& a, const float4 b) {
    a.x += b.x; a.y += b.y; a.z += b.z; a.w += b.w;
}

__device__ __forceinline__ uint32_t smem_u32(const void* p) {
    uint32_t a;
    asm("{ .reg .u64 t; cvta.to.shared.u64 t, %1; cvt.u32.u64 %0, t; }"
        : "=r"(a) : "l"(p));
    return a;
}
__device__ __forceinline__ void cpasync16(uint32_t s, const void* g) {
    asm volatile("cp.async.cg.shared.global [%0], [%1], 16;" :: "r"(s), "l"(g));
}
#define CP_COMMIT() asm volatile("cp.async.commit_group;")
#define CP_WAIT0()  asm volatile("cp.async.wait_group 0;")

// ---------------------------------------------------------------------------
// Inline table computation (inside K1's CTAs x<4, y==0; 512 entries per CTA).
// Branch-free FMAs on __ldg(U) (warp-uniform broadcast, L1-hot); runs while
// the CTA's cp.async fill is in flight.
// ---------------------------------------------------------------------------
__device__ __forceinline__ float bitf(int t, int q) {
    return (float)((t >> q) & 1);
}

__device__ void compute_tables_inline(const float* __restrict__ U,
                                      const float* __restrict__ detune)
{
    const int t = ((int)blockIdx.x << 9) + threadIdx.x;   // 0..2047
    const float det = __ldg(detune);

    float dlo0 = 0.f, dlo1 = 0.f;
#pragma unroll
    for (int p = 0; p < 11; p++) {
        float rs = -det;
#pragma unroll
        for (int q = 0; q < p; q++)
            rs = fmaf(bitf(t, q), __ldg(&U[(21 - p) * NQ + (21 - q)]), rs);
        if (p & 1) dlo1 = fmaf(bitf(t, p), rs, dlo1);
        else       dlo0 = fmaf(bitf(t, p), rs, dlo0);
    }
    g_dLo[t] = dlo0 + dlo1;

    float dhi0 = 0.f, dhi1 = 0.f;
#pragma unroll
    for (int h = 0; h < 11; h++) {
        float rs = -det;
#pragma unroll
        for (int h2 = 0; h2 < h; h2++)
            rs = fmaf(bitf(t, h2), __ldg(&U[(10 - h) * NQ + (10 - h2)]), rs);
        if (h & 1) dhi1 = fmaf(bitf(t, h), rs, dhi1);
        else       dhi0 = fmaf(bitf(t, h), rs, dhi0);
    }
    g_dHi[t] = dhi0 + dhi1;

#pragma unroll
    for (int h = 0; h < 11; h++) {
        float r0 = 0.f, r1 = 0.f;
#pragma unroll
        for (int q = 0; q < 11; q += 2)
            r0 = fmaf(bitf(t, q), __ldg(&U[(10 - h) * NQ + (21 - q)]), r0);
#pragma unroll
        for (int q = 1; q < 11; q += 2)
            r1 = fmaf(bitf(t, q), __ldg(&U[(10 - h) * NQ + (21 - q)]), r1);
        g_R[h][t] = r0 + r1;
    }
}

// ---------------------------------------------------------------------------
// K1 (RUNS FIRST): low bits 0..13 (14 X-neighbors), NO diag, NO RMW;
//   writes out = c*acc_low. Measured-fastest form — unchanged.
//   Component-split (blockIdx.y). Tile = 16384 consecutive elems = 64KB.
//   512 threads, 8 f4/thread reg-cached: G = tid + k*512 (k = bits 11..13).
//   bits 0..1: in-float4; bits 2..10: 9 smem dirs; bits 11..13: reg dirs.
//   CTAs (x<4, y==0) also build the diag tables for K2 behind their fill.
// ---------------------------------------------------------------------------
__global__ void __launch_bounds__(512, 2)
k1_low_kernel(const float* __restrict__ sr, const float* __restrict__ si,
              const float* __restrict__ rabi, float* __restrict__ out,
              const float* __restrict__ U, const float* __restrict__ detune)
{
    extern __shared__ float4 sv[];     // 4096 f4 = 64KB (one component)
    const uint32_t sb = smem_u32(sv);
    const int tid = threadIdx.x;
    const int comp = blockIdx.y;
    const float4* g4 = (const float4*)(comp ? si : sr);
    float4* o4 = (float4*)(out + (unsigned)comp * DIM);
    const unsigned gbase = (unsigned)blockIdx.x << 12;   // f4-group base

#pragma unroll
    for (int j = 0; j < 8; j++) {
        const int idx = tid + j * 512;
        cpasync16(sb + idx * 16, g4 + gbase + idx);
    }
    CP_COMMIT();
    const float c = 0.5f * __ldg(rabi);

    // side job: 4 CTAs build the diag tables for K2 while their fill flies
    if (blockIdx.x < 4 && comp == 0) compute_tables_inline(U, detune);

    CP_WAIT0();
    __syncthreads();

    float4 v[8];
#pragma unroll
    for (int k = 0; k < 8; k++) v[k] = sv[tid + k * 512];

#pragma unroll
    for (int k = 0; k < 8; k++) {
        const int G = tid + k * 512;
        const float4 s = v[k];

        // bits 0..1 (in-float4) + register dirs (bits 11..13)
        float4 a = make_float4(s.y + s.z, s.x + s.w, s.w + s.x, s.z + s.y);
        add4(a, v[k ^ 1]);
        add4(a, v[k ^ 2]);
        add4(a, v[k ^ 4]);

        // 9 smem dirs (bits 2..10), two waves to bound live temps
        float4 t0 = sv[G ^ 1],  t1 = sv[G ^ 2],  t2 = sv[G ^ 4];
        float4 t3 = sv[G ^ 8];
        add4(t0, t1); add4(t2, t3);
        add4(a, t0);  add4(a, t2);

        float4 u0 = sv[G ^ 16],  u1 = sv[G ^ 32],  u2 = sv[G ^ 64];
        float4 u3 = sv[G ^ 128], u4 = sv[G ^ 256];
        add4(u0, u1); add4(u2, u3);
        add4(u0, u2); add4(u4, a);
        add4(u4, u0);

        o4[gbase + G] = make_float4(c * u4.x, c * u4.y, c * u4.z, c * u4.w);
    }
}

// ---------------------------------------------------------------------------
// K2 (RUNS SECOND): high bits 14..21 (8 X-neighbors) + FULL diagonal; RMW:
//   out += c*acc_high + diag .* psi.
//   NEW vs R16: 256 threads x 8 f4/thread (same 32KB paired tile, same
//   global pattern) -> k = elem bits 19..21, THREE register dirs, 5 smem
//   dirs, an 8-deep o-load pipeline, and 4 CTAs/SM with staggered fills.
//   Tile: 8192 elems = bits 0..4 (32-elem rows) x bits 14..21 (256 combos);
//   mid = blockIdx.x = elem bits 5..13. idx = tid + k*256:
//     rf8 = tid&7, combo bits 0..4 = tid>>3, combo bits 5..7 = k.
//   bits 14..18: smem dirs idx^8..idx^128; bits 19..21: v[k^1],v[k^2],v[k^4].
//   diag: lo fixed per thread; hi = midtop | c5<<3 | k<<8.
//   base4 = dLo + midtop/c5-masked R rows (L1, behind the fill);
//   R[8]/R[9] per-k predicated L1 reloads (k compile-time); R[10] folded
//   into base4 at k==4; dHi scalar per k.
// ---------------------------------------------------------------------------
__global__ void __launch_bounds__(256, 4)
k2_high_kernel(const float* __restrict__ sr, const float* __restrict__ si,
               const float* __restrict__ rabi, float* __restrict__ out)
{
    extern __shared__ float4 sv[];     // 2048 f4 = 32KB (one component)
    const uint32_t sb = smem_u32(sv);
    const int tid = threadIdx.x;
    const int comp = blockIdx.y;
    const unsigned mid = blockIdx.x;                 // elem bits 5..13
    const float4* g4 = (const float4*)(comp ? si : sr);
    float4* o4 = (float4*)(out + (unsigned)comp * DIM);

    // global f4 index for thread's group k: gbase + k<<17
    const unsigned gbase = (((unsigned)tid >> 3) << 12) + (mid << 3) + (tid & 7u);

#pragma unroll
    for (int k = 0; k < 8; k++)
        cpasync16(sb + (tid + k * 256) * 16, g4 + gbase + ((unsigned)k << 17));
    CP_COMMIT();
    const float c = 0.5f * __ldg(rabi);

    // ---- diag staging (L1 loads, behind the fill) ----
    const int lo4 = (int)((mid & 63u) << 5) | ((tid & 7) << 2);  // elem bits 0..10
    const unsigned midtop = mid >> 6;                // hi bits 0..2
    const unsigned c5 = ((unsigned)tid >> 3) & 31u;  // hi bits 3..7
    float4 base4 = __ldg((const float4*)&g_dLo[lo4]);
    if (midtop & 1) add4(base4, __ldg((const float4*)&g_R[0][lo4]));
    if (midtop & 2) add4(base4, __ldg((const float4*)&g_R[1][lo4]));
    if (midtop & 4) add4(base4, __ldg((const float4*)&g_R[2][lo4]));
#pragma unroll
    for (int t = 0; t < 5; t++)
        if ((c5 >> t) & 1) add4(base4, __ldg((const float4*)&g_R[t + 3][lo4]));
    const unsigned hibase = midtop | (c5 << 3);

    CP_WAIT0();
    __syncthreads();

    float4 v[8];
#pragma unroll
    for (int k = 0; k < 8; k++) v[k] = sv[tid + k * 256];

#pragma unroll
    for (int k = 0; k < 8; k++) {
        if (k == 4) add4(base4, __ldg((const float4*)&g_R[10][lo4]));  // fold R10
        const int idx = tid + k * 256;
        const unsigned gG = gbase + ((unsigned)k << 17);

        // RMW load issued first; L2 latency overlaps the LDS block
        float4 o = o4[gG];

        // 5 smem dirs (elem bits 14..18), tight temp windows
        float4 t0 = sv[idx ^ 8],  t1 = sv[idx ^ 16];
        add4(t0, t1);
        float4 t2 = sv[idx ^ 32], t3 = sv[idx ^ 64];
        add4(t2, t3);
        add4(t0, t2);
        float4 t4 = sv[idx ^ 128];
        add4(t4, v[k ^ 1]);             // reg dir (bit 19)
        add4(t0, t4);
        add4(t0, v[k ^ 2]);             // reg dir (bit 20)
        add4(t0, v[k ^ 4]);             // reg dir (bit 21)

        // diagonal weight (k compile-time -> predicated L1 reloads are free)
        float4 W = base4;
        if (k & 1) add4(W, __ldg((const float4*)&g_R[8][lo4]));
        if (k & 2) add4(W, __ldg((const float4*)&g_R[9][lo4]));
        const float dh = __ldg(&g_dHi[hibase | ((unsigned)k << 8)]);
        W.x += dh; W.y += dh; W.z += dh; W.w += dh;

        o.x = fmaf(c, t0.x, fmaf(W.x, v[k].x, o.x));
        o.y = fmaf(c, t0.y, fmaf(W.y, v[k].y, o.y));
        o.z = fmaf(c, t0.z, fmaf(W.z, v[k].z, o.z));
        o.w = fmaf(c, t0.w, fmaf(W.w, v[k].w, o.w));
        o4[gG] = o;
    }
}

// ---------------------------------------------------------------------------
// Launch: K1 (bits 0..13, writes out; 4 CTAs build tables)
//      -> K2 (bits 14..21 + diag, RMW out; 256thr x 8f4, 4 CTAs/SM).
// ---------------------------------------------------------------------------
extern "C" void kernel_launch(void* const* d_in, const int* in_sizes, int n_in,
                              void* d_out, int out_size)
{
    const float* sr     = (const float*)d_in[0];
    const float* si     = (const float*)d_in[1];
    const float* rabi   = (const float*)d_in[2];
    const float* detune = (const float*)d_in[3];
    const float* U      = (const float*)d_in[4];
    float* out = (float*)d_out;

    cudaFuncSetAttribute(k1_low_kernel,
                         cudaFuncAttributeMaxDynamicSharedMemorySize, 65536);
    cudaFuncSetAttribute(k2_high_kernel,
                         cudaFuncAttributeMaxDynamicSharedMemorySize, 32768);

    k1_low_kernel<<<dim3(256, 2), 512, 65536>>>(sr, si, rabi, out, U, detune);
    k2_high_kernel<<<dim3(512, 2), 256, 32768>>>(sr, si, rabi, out);
}